// round 11
// baseline (speedup 1.0000x reference)
#include <cuda_runtime.h>
#include <cuda_fp16.h>
#include <cstdint>

#define N_NODES 20000
#define N_EDGES 320000
#define F_NODE 64
#define F_EDGE 16
#define HID 300
#define N_GRAPHS 128

#define MODE_INIT 0
#define MODE_CONV 1

#define N_PAD 320
#define KCHUNK 32
#define TOTAL_WCHUNKS 45                      // 3 init + 10*3 conv + 12 e2n
#define WCHUNK_ELEMS (N_PAD * KCHUNK)         // 10240
#define WCHUNK_BYTES (WCHUNK_ELEMS * 2)       // 20480

#define NTHREADS 640
#define PERSIST_GRID 152

// persistent kernel SMEM: A tiles [0,8192) = 2 x 4KB, B [8192, 8192+C*20480)
#define SMEM_A_OFF 0
#define SMEM_B_OFF 8192
#define SMEM_PERSIST(C) (SMEM_B_OFF + (C) * WCHUNK_BYTES)
// streaming e2n SMEM: A [0,8192), B [8192,49152) = 2 x 20KB
#define SMEM_E2N 49152

// ---------------- scratch (device globals; no allocations allowed) -------------
__device__ __half g_h0[(size_t)N_EDGES * HID];   // 192 MB
__device__ __half g_hA[(size_t)N_EDGES * HID];   // 192 MB
__device__ __half g_hB[(size_t)N_EDGES * HID];   // 192 MB
// 4 scatter accumulators + pooled, contiguous for one-shot zeroing
#define NA (N_NODES * HID)
__device__ float  g_acc[4 * NA + N_GRAPHS * HID];
__device__ __align__(16) unsigned char g_W[(size_t)TOTAL_WCHUNKS * WCHUNK_BYTES];

// ---------------- helpers ----------------
__device__ __forceinline__ uint32_t smem_to_u32(const void* p) {
    uint32_t a;
    asm("{ .reg .u64 t; cvta.to.shared.u64 t, %1; cvt.u32.u64 %0, t; }" : "=r"(a) : "l"(p));
    return a;
}

#define LDSM_X4(r, addr) \
    asm volatile("ldmatrix.sync.aligned.m8n8.x4.shared.b16 {%0,%1,%2,%3}, [%4];" \
                 : "=r"((r)[0]), "=r"((r)[1]), "=r"((r)[2]), "=r"((r)[3]) : "r"(addr))

#define MMA_F16(d, a, b) \
    asm volatile("mma.sync.aligned.m16n8k16.row.col.f32.f16.f16.f32 " \
                 "{%0,%1,%2,%3}, {%4,%5,%6,%7}, {%8,%9}, {%0,%1,%2,%3};" \
                 : "+f"((d)[0]), "+f"((d)[1]), "+f"((d)[2]), "+f"((d)[3]) \
                 : "r"((a)[0]), "r"((a)[1]), "r"((a)[2]), "r"((a)[3]), \
                   "r"((b)[0]), "r"((b)[1]))

#define CP_ASYNC16(dst, src) \
    asm volatile("cp.async.cg.shared.global [%0], [%1], 16;" \
                 :: "r"(dst), "l"(src) : "memory")
#define CP_COMMIT() asm volatile("cp.async.commit_group;" ::: "memory")
#define CP_WAIT0()  asm volatile("cp.async.wait_group 0;" ::: "memory")

__device__ __forceinline__ uint32_t pack_h2(float a, float b) {
    __half2 h = __floats2half2_rn(a, b);
    return *(uint32_t*)&h;
}
__device__ __forceinline__ float2 unpack_h2(uint32_t u) {
    __half2 h = *(__half2*)&u;
    return __half22float2(h);
}

// 64B-row XOR swizzle: 16B group g at row r lands at group g ^ ((r>>1)&3)
__device__ __host__ __forceinline__ uint32_t swzoff(uint32_t row, uint32_t grp) {
    return row * 64u + ((grp ^ ((row >> 1) & 3u)) << 4);
}

struct Pref { float4 a0; uint2 h0v; };

// ---------------- weight prep: fp16 + transpose + N-permute + swizzle ----------
__global__ void prep_weights(const float* __restrict__ Wi,
                             const float* __restrict__ Wc,
                             const float* __restrict__ We) {
    int idx = blockIdx.x * blockDim.x + threadIdx.x;
    if (idx >= TOTAL_WCHUNKS * WCHUNK_ELEMS) return;
    int chunk = idx / WCHUNK_ELEMS;
    int rem   = idx % WCHUNK_ELEMS;
    int n_log = rem >> 5;       // 0..319
    int k     = rem & 31;       // 0..31
    const float* W; int K; int c;
    if (chunk < 3)       { W = Wi;               K = F_NODE + F_EDGE; c = chunk; }
    else if (chunk < 13) { W = Wc + 0 * HID*HID; K = HID;             c = chunk - 3; }
    else if (chunk < 23) { W = Wc + 1 * HID*HID; K = HID;             c = chunk - 13; }
    else if (chunk < 33) { W = Wc + 2 * HID*HID; K = HID;             c = chunk - 23; }
    else                 { W = We;               K = F_NODE + HID;    c = chunk - 33; }
    int ka = c * KCHUNK + k;
    float v = (ka < K && n_log < HID) ? W[(size_t)ka * HID + n_log] : 0.f;
    // permutation: n_log = p*16 + q*4 + r  ->  n_phys = p*16 + (r>>1)*8 + q*2 + (r&1)
    int p = n_log >> 4, q = (n_log >> 2) & 3, r = n_log & 3;
    int n_phys = p * 16 + (r >> 1) * 8 + q * 2 + (r & 1);
    uint32_t off = swzoff((uint32_t)n_phys, (uint32_t)(k >> 3)) + (uint32_t)((k & 7) * 2);
    *(__half*)(g_W + (size_t)chunk * WCHUNK_BYTES + off) = __float2half_rn(v);
}

// ---------------- persistent fused HMMA kernel (INIT / CONV) ----------------
// grid = 152 persistent CTAs; whole weight layer (C chunks) resident in SMEM.
// Per tile: 64 rows x full N=320; A double-buffered via LDG->regs->STS.
// Warp grid 2(M) x 10(N); warp tile 32x32; mma.sync m16n8k16 f16.
template<int MODE, int K, int C, int WBASE, bool WRITE_H>
__global__ __launch_bounds__(NTHREADS, 1)
void fused_persist(const float* __restrict__ x,
                   const float* __restrict__ edge_attr,
                   const int*   __restrict__ rowIdx,
                   const int*   __restrict__ scat_idx,
                   const float* __restrict__ aIn,
                   const __half* __restrict__ hIn,
                   const float* __restrict__ bias,
                   const __half* __restrict__ h0,
                   __half* __restrict__ hOut,
                   float* __restrict__ scatterOut,
                   int numTiles) {
    extern __shared__ char smem[];
    const uint32_t smem_u = smem_to_u32(smem);
    const int tid = threadIdx.x;
    const int lane = tid & 31;
    const int wid  = tid >> 5;
    const int wm   = wid / 10;    // 0..1
    const int wn   = wid % 10;    // 0..9
    const int r = tid >> 3;       // 0..63 (stagers)
    const int q = tid & 7;        // 0..7
    const bool stager = (tid < 512);

    // ---- load the whole weight layer into SMEM once ----
    {
        const unsigned char* src = g_W + (size_t)WBASE * WCHUNK_BYTES;
        const uint32_t dst = smem_u + SMEM_B_OFF;
        for (int off = tid * 16; off < C * WCHUNK_BYTES; off += NTHREADS * 16)
            CP_ASYNC16(dst + off, src + off);
        CP_COMMIT(); CP_WAIT0();
    }
    __syncthreads();

    for (int tile = blockIdx.x; tile < numTiles; tile += gridDim.x) {
        const int bm = tile * 64;
        const int m_st = bm + r;

        // per-tile row pointers in registers (no smem indices, no extra syncs)
        const float*  aRow = nullptr;
        const __half* hRow = nullptr;
        const float*  xRow = nullptr;
        const float*  eRow = nullptr;
        if (stager) {
            const int nr = rowIdx[m_st];
            if (MODE == MODE_CONV) {
                aRow = aIn + (size_t)nr * HID;
                hRow = hIn + (size_t)(bm + (r ^ 1)) * HID;
            } else {
                xRow = x + (size_t)nr * F_NODE;
                eRow = edge_attr + (size_t)m_st * F_EDGE;
            }
        }

        auto loadA = [&](int c) -> Pref {
            Pref pf;
            pf.a0 = make_float4(0.f, 0.f, 0.f, 0.f);
            pf.h0v = make_uint2(0u, 0u);
            if (!stager) return pf;
            const int ka = c * KCHUNK + q * 4;
            if (MODE == MODE_CONV) {
                if (ka + 4 <= K) {
                    pf.a0  = *(const float4*)(aRow + ka);
                    pf.h0v = *(const uint2*)(hRow + ka);
                }
            } else {
                if (ka + 4 <= F_NODE)
                    pf.a0 = *(const float4*)(xRow + ka);
                else if (ka >= F_NODE && ka + 4 <= F_NODE + F_EDGE)
                    pf.a0 = *(const float4*)(eRow + (ka - F_NODE));
            }
            return pf;
        };
        auto storeA = [&](int buf, const Pref& pf) {
            if (!stager) return;
            uint2 h;
            if (MODE == MODE_CONV) {
                float2 h0a = unpack_h2(pf.h0v.x), h0b = unpack_h2(pf.h0v.y);
                h.x = pack_h2(pf.a0.x - h0a.x, pf.a0.y - h0a.y);
                h.y = pack_h2(pf.a0.z - h0b.x, pf.a0.w - h0b.y);
            } else {
                h.x = pack_h2(pf.a0.x, pf.a0.y);
                h.y = pack_h2(pf.a0.z, pf.a0.w);
            }
            const uint32_t off = swzoff((uint32_t)r, (uint32_t)(q >> 1)) + (uint32_t)((q & 1) * 8);
            *(uint2*)(smem + SMEM_A_OFF + buf * 4096 + off) = h;
        };

        float acc[32];
        #pragma unroll
        for (int i = 0; i < 32; i++) acc[i] = 0.f;

        Pref pf = loadA(0);
        storeA(0, pf);
        __syncthreads();

        for (int c = 0; c < C; c++) {
            const bool more = (c + 1 < C);
            if (more) pf = loadA(c + 1);
            // ---- MMA on A buf (c&1), resident B chunk c ----
            {
                const uint32_t At = smem_u + SMEM_A_OFF + (c & 1) * 4096;
                const uint32_t Bt = smem_u + SMEM_B_OFF + c * WCHUNK_BYTES;
                #pragma unroll
                for (int ks = 0; ks < 2; ks++) {
                    uint32_t af[2][4];
                    const uint32_t agrp = (uint32_t)(ks * 2 + (lane >> 4));
                    #pragma unroll
                    for (int mt = 0; mt < 2; mt++) {
                        const uint32_t row = (uint32_t)(wm * 32 + mt * 16 + (lane & 15));
                        LDSM_X4(af[mt], At + swzoff(row, agrp));
                    }
                    #pragma unroll
                    for (int pg = 0; pg < 2; pg++) {
                        const uint32_t nrow = (uint32_t)(wn * 32 + pg * 16 + ((lane >> 4) << 3) + (lane & 7));
                        const uint32_t bgrp = (uint32_t)(ks * 2 + ((lane >> 3) & 1));
                        uint32_t bf[4];
                        LDSM_X4(bf, Bt + swzoff(nrow, bgrp));
                        #pragma unroll
                        for (int mt = 0; mt < 2; mt++)
                            #pragma unroll
                            for (int nt = 0; nt < 2; nt++)
                                MMA_F16(&acc[((mt * 2 + pg) * 2 + nt) * 4], af[mt], &bf[nt * 2]);
                    }
                }
            }
            if (more) { storeA((c + 1) & 1, pf); __syncthreads(); }
        }

        // ---- epilogue: bias + skip + relu, fp16 h write, fp32 scatter-add ----
        #pragma unroll
        for (int mt = 0; mt < 2; mt++) {
            #pragma unroll
            for (int rh = 0; rh < 2; rh++) {
                const int m = bm + wm * 32 + mt * 16 + (lane >> 2) + rh * 8;
                const int sc = scat_idx[m];
                const __half* h0r = h0 + (size_t)m * HID;
                __half* hor = hOut + (size_t)m * HID;
                float* scr = scatterOut + (size_t)sc * HID;
                #pragma unroll
                for (int pg = 0; pg < 2; pg++) {
                    const int n = wn * 32 + pg * 16 + (lane & 3) * 4;
                    if (n >= HID) continue;
                    const float* d0 = &acc[((mt * 2 + pg) * 2 + 0) * 4];
                    const float* d1 = &acc[((mt * 2 + pg) * 2 + 1) * 4];
                    float4 v;
                    v.x = d0[rh * 2 + 0]; v.y = d0[rh * 2 + 1];
                    v.z = d1[rh * 2 + 0]; v.w = d1[rh * 2 + 1];
                    const float4 bb = __ldg((const float4*)(bias + n));
                    v.x += bb.x; v.y += bb.y; v.z += bb.z; v.w += bb.w;
                    if (MODE == MODE_CONV) {
                        const uint2 sr = *(const uint2*)(h0r + n);
                        float2 s0 = unpack_h2(sr.x), s1 = unpack_h2(sr.y);
                        v.x += s0.x; v.y += s0.y; v.z += s1.x; v.w += s1.y;
                    }
                    v.x = fmaxf(v.x, 0.f); v.y = fmaxf(v.y, 0.f);
                    v.z = fmaxf(v.z, 0.f); v.w = fmaxf(v.w, 0.f);
                    if (WRITE_H) {
                        uint2 hw;
                        hw.x = pack_h2(v.x, v.y);
                        hw.y = pack_h2(v.z, v.w);
                        *(uint2*)(hor + n) = hw;
                    }
                    asm volatile("red.global.add.v4.f32 [%0], {%1, %2, %3, %4};"
                                 :: "l"(scr + n), "f"(v.x), "f"(v.y), "f"(v.z), "f"(v.w)
                                 : "memory");
                }
            }
        }
        __syncthreads();   // A buffers free for next tile
    }
}

// ---------------- streaming e2n kernel (K=364 pad 384, C=12, WBASE=33) --------
__global__ __launch_bounds__(NTHREADS, 1)
void fused_e2n(const float* __restrict__ x,
               const int*   __restrict__ batch,
               const float* __restrict__ sIn,
               const float* __restrict__ bias,
               float* __restrict__ pooled,
               int M) {
    constexpr int K = F_NODE + HID;   // 364
    constexpr int C = 12;
    constexpr int WBASE = 33;
    extern __shared__ char smem[];
    const uint32_t smem_u = smem_to_u32(smem);
    const int tid = threadIdx.x;
    const int bm = blockIdx.x * 64;
    const int lane = tid & 31;
    const int wid  = tid >> 5;
    const int wm   = wid / 10;
    const int wn   = wid % 10;
    const int r = tid >> 3;
    const int q = tid & 7;
    const int m_st = bm + r;
    const bool stager = (tid < 512);

    float acc[32];
    #pragma unroll
    for (int i = 0; i < 32; i++) acc[i] = 0.f;

    auto loadA = [&](int c) -> float4 {
        float4 a = make_float4(0.f, 0.f, 0.f, 0.f);
        if (!stager || m_st >= M) return a;
        const int ka = c * KCHUNK + q * 4;
        if (ka + 4 <= F_NODE)
            a = *(const float4*)(x + (size_t)m_st * F_NODE + ka);
        else if (ka >= F_NODE && ka - F_NODE + 4 <= HID)
            a = *(const float4*)(sIn + (size_t)m_st * HID + (ka - F_NODE));
        return a;
    };
    auto storeA = [&](int buf, const float4& a) {
        if (!stager) return;
        uint2 h;
        h.x = pack_h2(a.x, a.y);
        h.y = pack_h2(a.z, a.w);
        const uint32_t off = swzoff((uint32_t)r, (uint32_t)(q >> 1)) + (uint32_t)((q & 1) * 8);
        *(uint2*)(smem + SMEM_A_OFF + buf * 4096 + off) = h;
    };
    auto issueB = [&](int c, int buf) {
        const unsigned char* src = g_W + (size_t)(WBASE + c) * WCHUNK_BYTES;
        const uint32_t dst = smem_u + SMEM_B_OFF + buf * WCHUNK_BYTES;
        CP_ASYNC16(dst + tid * 16, src + tid * 16);
        CP_ASYNC16(dst + (tid + NTHREADS) * 16, src + (tid + NTHREADS) * 16);
    };
    auto mmaChunk = [&](int buf) {
        const uint32_t At = smem_u + SMEM_A_OFF + buf * 4096;
        const uint32_t Bt = smem_u + SMEM_B_OFF + buf * WCHUNK_BYTES;
        #pragma unroll
        for (int ks = 0; ks < 2; ks++) {
            uint32_t af[2][4];
            const uint32_t agrp = (uint32_t)(ks * 2 + (lane >> 4));
            #pragma unroll
            for (int mt = 0; mt < 2; mt++) {
                const uint32_t row = (uint32_t)(wm * 32 + mt * 16 + (lane & 15));
                LDSM_X4(af[mt], At + swzoff(row, agrp));
            }
            #pragma unroll
            for (int pg = 0; pg < 2; pg++) {
                const uint32_t nrow = (uint32_t)(wn * 32 + pg * 16 + ((lane >> 4) << 3) + (lane & 7));
                const uint32_t bgrp = (uint32_t)(ks * 2 + ((lane >> 3) & 1));
                uint32_t bf[4];
                LDSM_X4(bf, Bt + swzoff(nrow, bgrp));
                #pragma unroll
                for (int mt = 0; mt < 2; mt++)
                    #pragma unroll
                    for (int nt = 0; nt < 2; nt++)
                        MMA_F16(&acc[((mt * 2 + pg) * 2 + nt) * 4], af[mt], &bf[nt * 2]);
            }
        }
    };

    {
        float4 a0 = loadA(0);
        issueB(0, 0);
        storeA(0, a0);
        CP_COMMIT(); CP_WAIT0();
    }
    __syncthreads();

    for (int c = 0; c < C; c++) {
        const int buf = c & 1;
        float4 an;
        const bool more = (c + 1 < C);
        if (more) {
            an = loadA(c + 1);
            issueB(c + 1, buf ^ 1);
            CP_COMMIT();
        }
        mmaChunk(buf);
        if (more) {
            storeA(buf ^ 1, an);
            CP_WAIT0();
            __syncthreads();
        }
    }

    #pragma unroll
    for (int mt = 0; mt < 2; mt++) {
        #pragma unroll
        for (int rh = 0; rh < 2; rh++) {
            const int m = bm + wm * 32 + mt * 16 + (lane >> 2) + rh * 8;
            if (m >= M) continue;
            const int sc = batch[m];
            float* scr = pooled + (size_t)sc * HID;
            #pragma unroll
            for (int pg = 0; pg < 2; pg++) {
                const int n = wn * 32 + pg * 16 + (lane & 3) * 4;
                if (n >= HID) continue;
                const float* d0 = &acc[((mt * 2 + pg) * 2 + 0) * 4];
                const float* d1 = &acc[((mt * 2 + pg) * 2 + 1) * 4];
                float4 v;
                v.x = d0[rh * 2 + 0]; v.y = d0[rh * 2 + 1];
                v.z = d1[rh * 2 + 0]; v.w = d1[rh * 2 + 1];
                const float4 bb = __ldg((const float4*)(bias + n));
                v.x += bb.x; v.y += bb.y; v.z += bb.z; v.w += bb.w;
                v.x = fmaxf(v.x, 0.f); v.y = fmaxf(v.y, 0.f);
                v.z = fmaxf(v.z, 0.f); v.w = fmaxf(v.w, 0.f);
                asm volatile("red.global.add.v4.f32 [%0], {%1, %2, %3, %4};"
                             :: "l"(scr + n), "f"(v.x), "f"(v.y), "f"(v.z), "f"(v.w)
                             : "memory");
            }
        }
    }
}

__global__ void zero_kernel(float4* __restrict__ p, int n4) {
    int i = blockIdx.x * blockDim.x + threadIdx.x;
    if (i < n4) p[i] = make_float4(0.f, 0.f, 0.f, 0.f);
}

__global__ void ffn_kernel(const float* __restrict__ pooled,
                           const float* __restrict__ W,
                           const float* __restrict__ b,
                           float* __restrict__ out) {
    int g = blockIdx.x;
    int lane = threadIdx.x;
    float s = 0.f;
    for (int k = lane; k < HID; k += 32)
        s += pooled[g * HID + k] * W[k];
    #pragma unroll
    for (int o = 16; o > 0; o >>= 1)
        s += __shfl_xor_sync(0xFFFFFFFFu, s, o);
    if (lane == 0) out[g] = s + b[0];
}

extern "C" void kernel_launch(void* const* d_in, const int* in_sizes, int n_in,
                              void* d_out, int out_size) {
    const float* x         = (const float*)d_in[0];
    const float* edge_attr = (const float*)d_in[1];
    const int*   edge_idx  = (const int*)  d_in[2];
    const int*   batch     = (const int*)  d_in[3];
    const float* W_init    = (const float*)d_in[4];
    const float* b_init    = (const float*)d_in[5];
    const float* W_convs   = (const float*)d_in[6];
    const float* b_convs   = (const float*)d_in[7];
    const float* W_e2n     = (const float*)d_in[8];
    const float* b_e2n     = (const float*)d_in[9];
    const float* W_ffn     = (const float*)d_in[10];
    const float* b_ffn     = (const float*)d_in[11];
    float* out = (float*)d_out;

    const int* row = edge_idx;
    const int* col = edge_idx + N_EDGES;

    __half *h0, *hA, *hB;
    float *acc;
    cudaGetSymbolAddress((void**)&h0, g_h0);
    cudaGetSymbolAddress((void**)&hA, g_hA);
    cudaGetSymbolAddress((void**)&hB, g_hB);
    cudaGetSymbolAddress((void**)&acc, g_acc);
    float* aInit  = acc + 0 * NA;
    float* a0     = acc + 1 * NA;
    float* a1     = acc + 2 * NA;
    float* a2     = acc + 3 * NA;
    float* pooled = acc + 4 * NA;

    cudaFuncSetAttribute(fused_persist<MODE_INIT, F_NODE + F_EDGE, 3, 0, true>,
                         cudaFuncAttributeMaxDynamicSharedMemorySize, SMEM_PERSIST(3));
    cudaFuncSetAttribute(fused_persist<MODE_CONV, HID, 10, 3, true>,
                         cudaFuncAttributeMaxDynamicSharedMemorySize, SMEM_PERSIST(10));
    cudaFuncSetAttribute(fused_persist<MODE_CONV, HID, 10, 13, true>,
                         cudaFuncAttributeMaxDynamicSharedMemorySize, SMEM_PERSIST(10));
    cudaFuncSetAttribute(fused_persist<MODE_CONV, HID, 10, 23, false>,
                         cudaFuncAttributeMaxDynamicSharedMemorySize, SMEM_PERSIST(10));
    cudaFuncSetAttribute(fused_e2n,
                         cudaFuncAttributeMaxDynamicSharedMemorySize, SMEM_E2N);

    const int numTilesE = N_EDGES / 64;            // 5000
    const int gN = (N_NODES + 63) / 64;            // 313
    const int totalZero4 = (4 * NA + N_GRAPHS * HID) / 4;

    // [0] weight preprocessing
    prep_weights<<<(TOTAL_WCHUNKS * WCHUNK_ELEMS + 255) / 256, 256>>>(W_init, W_convs, W_e2n);

    // [1] zero all scatter accumulators + pooled in one launch
    zero_kernel<<<(totalZero4 + 255) / 256, 256>>>((float4*)acc, totalZero4);

    // [2] init: h0 = relu(cat(x[row], edge_attr) @ W_init + b); scatter -> aInit
    fused_persist<MODE_INIT, F_NODE + F_EDGE, 3, 0, true>
        <<<PERSIST_GRID, NTHREADS, SMEM_PERSIST(3)>>>(
        x, edge_attr, row, col, nullptr, nullptr, b_init, h0, h0, aInit, numTilesE);

    // [3] conv0: A = aInit[row] - rev(h0); h = relu(A@W0 + b0 + h0); scatter -> a0
    fused_persist<MODE_CONV, HID, 10, 3, true>
        <<<PERSIST_GRID, NTHREADS, SMEM_PERSIST(10)>>>(
        nullptr, nullptr, row, col, aInit, h0, b_convs + 0 * HID, h0, hA, a0, numTilesE);

    // [4] conv1: reads a0, hA -> hB; scatter -> a1
    fused_persist<MODE_CONV, HID, 10, 13, true>
        <<<PERSIST_GRID, NTHREADS, SMEM_PERSIST(10)>>>(
        nullptr, nullptr, row, col, a0, hA, b_convs + 1 * HID, h0, hB, a1, numTilesE);

    // [5] conv2: reads a1, hB; scatter only -> a2 (= s)   <-- ncu -s 5 captures this
    fused_persist<MODE_CONV, HID, 10, 23, false>
        <<<PERSIST_GRID, NTHREADS, SMEM_PERSIST(10)>>>(
        nullptr, nullptr, row, col, a1, hB, b_convs + 2 * HID, h0, hA, a2, numTilesE);

    // [6] e2n: hn = relu(cat(x, s) @ W_e2n + b); scatter by batch -> pooled
    fused_e2n<<<gN, NTHREADS, SMEM_E2N>>>(x, batch, a2, b_e2n, pooled, N_NODES);

    // [7] out = pooled @ W_ffn + b
    ffn_kernel<<<N_GRAPHS, 32>>>(pooled, W_ffn, b_ffn, out);
}